// round 7
// baseline (speedup 1.0000x reference)
#include <cuda_runtime.h>
#include <cuda_bf16.h>
#include <cfloat>
#include <climits>
#include <cstdint>

// ---------------------------------------------------------------------------
// Problem shape (fixed):
//   query [B=256,1024] f32, bank [M=200000,1024] f32, traj [M,8,3] f32, k=16
// Output: traj[nn_idx] sorted by ascending L2 dist, ties -> lower index.
// Strategy: bf16 mma.sync coarse scores -> segmented top-64 candidate select
// -> exact fp32 rescore -> top-16 -> gather.
// ---------------------------------------------------------------------------

#define C_DIM   1024
#define B_MAX   256
#define M_MAX   200000
#define KSEL    16
#define NCAND   64
#define NSEG    16

// __device__ scratch (allocation-free rule)
__device__ __align__(16) float          g_score[(size_t)B_MAX * M_MAX];
__device__ __align__(16) float          g_bsq[M_MAX];
__device__ __align__(16) __nv_bfloat16  g_bank_bf[(size_t)M_MAX * C_DIM];
__device__ __align__(16) __nv_bfloat16  g_q_bf[(size_t)B_MAX * C_DIM];
__device__ __align__(16) unsigned long long g_seg[(size_t)B_MAX * NSEG * NCAND];
__device__                int           g_cand[B_MAX * NCAND];

#define SMEM_SWIZZLE_128B(o) ((o) ^ (((o) >> 3) & 0x70))

__device__ __forceinline__ uint32_t smem_to_u32(const void* p) {
    uint32_t a;
    asm("{ .reg .u64 t; cvta.to.shared.u64 t, %1; cvt.u32.u64 %0, t; }"
        : "=r"(a) : "l"(p));
    return a;
}
__device__ __forceinline__ void cp_async16(uint32_t dst, const void* src, int srcsize) {
    asm volatile("cp.async.cg.shared.global [%0], [%1], 16, %2;"
                 :: "r"(dst), "l"(src), "r"(srcsize));
}
__device__ __forceinline__ void cp_commit() {
    asm volatile("cp.async.commit_group;");
}
template <int N>
__device__ __forceinline__ void cp_wait() {
    asm volatile("cp.async.wait_group %0;" :: "n"(N));
}
__device__ __forceinline__ void ldmx4(uint32_t& r0, uint32_t& r1,
                                      uint32_t& r2, uint32_t& r3, uint32_t addr) {
    asm volatile("ldmatrix.sync.aligned.m8n8.x4.shared.b16 {%0,%1,%2,%3}, [%4];"
                 : "=r"(r0), "=r"(r1), "=r"(r2), "=r"(r3) : "r"(addr));
}
__device__ __forceinline__ void mma16816(float* c, const uint32_t* a, const uint32_t* b) {
    asm volatile(
        "mma.sync.aligned.m16n8k16.row.col.f32.bf16.bf16.f32 "
        "{%0,%1,%2,%3}, {%4,%5,%6,%7}, {%8,%9}, {%0,%1,%2,%3};"
        : "+f"(c[0]), "+f"(c[1]), "+f"(c[2]), "+f"(c[3])
        : "r"(a[0]), "r"(a[1]), "r"(a[2]), "r"(a[3]), "r"(b[0]), "r"(b[1]));
}

// ---------------------------------------------------------------------------
// Kernel 1: fp32 -> bf16 convert, fused squared norms. One warp per row.
// ---------------------------------------------------------------------------
__global__ void convert_kernel(const float* __restrict__ src,
                               __nv_bfloat16* __restrict__ dst,
                               float* __restrict__ bsq, int rows) {
    int warp = (blockIdx.x * blockDim.x + threadIdx.x) >> 5;
    int lane = threadIdx.x & 31;
    if (warp >= rows) return;
    const float4* srow = reinterpret_cast<const float4*>(src + (size_t)warp * C_DIM);
    __nv_bfloat162* drow = reinterpret_cast<__nv_bfloat162*>(dst + (size_t)warp * C_DIM);
    float acc = 0.f;
#pragma unroll
    for (int i = 0; i < C_DIM / 128; i++) {
        int j = i * 32 + lane;
        float4 v = srow[j];
        acc += v.x * v.x + v.y * v.y + v.z * v.z + v.w * v.w;
        drow[2 * j]     = __nv_bfloat162(__float2bfloat16(v.x), __float2bfloat16(v.y));
        drow[2 * j + 1] = __nv_bfloat162(__float2bfloat16(v.z), __float2bfloat16(v.w));
    }
    if (bsq) {
#pragma unroll
        for (int off = 16; off > 0; off >>= 1)
            acc += __shfl_xor_sync(0xffffffffu, acc, off);
        if (lane == 0) bsq[warp] = acc;
    }
}

// ---------------------------------------------------------------------------
// Kernel 2: coarse bf16 GEMM via mma.sync.m16n8k16. (unchanged from R6)
// ---------------------------------------------------------------------------
#define BM   128
#define BN   128
#define BKC  64
#define NCH  (C_DIM / BKC)
#define TILE_BYTES (BM * 128)
#define GEMM_SMEM  (4 * TILE_BYTES)

__global__ __launch_bounds__(256, 2)
void mma_gemm_kernel(int M) {
    extern __shared__ char smem[];
    const uint32_t sb = smem_to_u32(smem);
    const int tid  = threadIdx.x;
    const int wid  = tid >> 5;
    const int lane = tid & 31;
    const int qt = blockIdx.x;
    const int bn = blockIdx.y * BN;
    const int warp_m = wid & 1;
    const int warp_n = wid >> 1;

    const __nv_bfloat16* Abase = g_q_bf + (size_t)qt * BM * C_DIM;

    int lrow[4], lu[4];
#pragma unroll
    for (int l = 0; l < 4; l++) {
        int id = tid + l * 256;
        lrow[l] = id >> 3;
        lu[l]   = id & 7;
    }

    auto issue_loads = [&](int c, int buf) {
        int k0 = c * BKC;
        uint32_t As = sb + buf * 2 * TILE_BYTES;
        uint32_t Bs = As + TILE_BYTES;
#pragma unroll
        for (int l = 0; l < 4; l++) {
            uint32_t so = SMEM_SWIZZLE_128B((uint32_t)(lrow[l] * 128 + lu[l] * 16));
            cp_async16(As + so, Abase + (size_t)lrow[l] * C_DIM + k0 + lu[l] * 8, 16);
            int n = bn + lrow[l];
            const void* srcB = g_bank_bf + (size_t)(n < M ? n : 0) * C_DIM + k0 + lu[l] * 8;
            cp_async16(Bs + so, srcB, n < M ? 16 : 0);
        }
        cp_commit();
    };

    float acc[4][4][4];
#pragma unroll
    for (int mi = 0; mi < 4; mi++)
#pragma unroll
        for (int nj = 0; nj < 4; nj++)
#pragma unroll
            for (int e = 0; e < 4; e++) acc[mi][nj][e] = 0.f;

    issue_loads(0, 0);

    for (int c = 0; c < NCH; c++) {
        int buf = c & 1;
        if (c + 1 < NCH) {
            issue_loads(c + 1, buf ^ 1);
            cp_wait<1>();
        } else {
            cp_wait<0>();
        }
        __syncthreads();

        uint32_t As = sb + buf * 2 * TILE_BYTES;
        uint32_t Bs = As + TILE_BYTES;
#pragma unroll
        for (int ks = 0; ks < BKC / 16; ks++) {
            uint32_t a[4][4];
            int arow = warp_m * 64 + (lane & 15);
            int akb  = ks * 16 + (lane >> 4) * 8;
#pragma unroll
            for (int mi = 0; mi < 4; mi++) {
                uint32_t so = SMEM_SWIZZLE_128B(
                    (uint32_t)((arow + mi * 16) * 128 + akb * 2));
                ldmx4(a[mi][0], a[mi][1], a[mi][2], a[mi][3], As + so);
            }
            uint32_t b[4][2];
            int g = lane >> 3;
#pragma unroll
            for (int pair = 0; pair < 2; pair++) {
                int brow = warp_n * 32 + pair * 16 + ((g >> 1) & 1) * 8 + (lane & 7);
                int bkb  = ks * 16 + (g & 1) * 8;
                uint32_t so = SMEM_SWIZZLE_128B((uint32_t)(brow * 128 + bkb * 2));
                uint32_t r0, r1, r2, r3;
                ldmx4(r0, r1, r2, r3, Bs + so);
                b[2 * pair][0] = r0; b[2 * pair][1] = r1;
                b[2 * pair + 1][0] = r2; b[2 * pair + 1][1] = r3;
            }
#pragma unroll
            for (int mi = 0; mi < 4; mi++)
#pragma unroll
                for (int nj = 0; nj < 4; nj++)
                    mma16816(acc[mi][nj], a[mi], b[nj]);
        }
        __syncthreads();
    }

    const int qbase = qt * BM + warp_m * 64;
    const int nbase = bn + warp_n * 32;
#pragma unroll
    for (int mi = 0; mi < 4; mi++) {
#pragma unroll
        for (int nj = 0; nj < 4; nj++) {
            int n0 = nbase + nj * 8 + (lane & 3) * 2;
            if (n0 + 1 < M) {
                float b0 = g_bsq[n0], b1 = g_bsq[n0 + 1];
                int q0 = qbase + mi * 16 + (lane >> 2);
                float2 v0 = make_float2(b0 - 2.f * acc[mi][nj][0],
                                        b1 - 2.f * acc[mi][nj][1]);
                float2 v1 = make_float2(b0 - 2.f * acc[mi][nj][2],
                                        b1 - 2.f * acc[mi][nj][3]);
                *reinterpret_cast<float2*>(g_score + (size_t)q0 * M + n0) = v0;
                *reinterpret_cast<float2*>(g_score + (size_t)(q0 + 8) * M + n0) = v1;
            } else if (n0 < M) {
                float b0 = g_bsq[n0];
                int q0 = qbase + mi * 16 + (lane >> 2);
                g_score[(size_t)q0 * M + n0]       = b0 - 2.f * acc[mi][nj][0];
                g_score[(size_t)(q0 + 8) * M + n0] = b0 - 2.f * acc[mi][nj][2];
            }
        }
    }
}

// ---------------------------------------------------------------------------
// Selection helpers
// ---------------------------------------------------------------------------
__device__ __forceinline__ unsigned long long pack_key(float s, int idx) {
    unsigned u = __float_as_uint(s);
    u = (u & 0x80000000u) ? ~u : (u | 0x80000000u);
    return ((unsigned long long)u << 32) | (unsigned)idx;
}

// ---------------------------------------------------------------------------
// Kernel 3a: segmented coarse selection. grid = (NSEG, B).
// Each CTA: streaming thread-local top-8 over its segment, 2048-key bitonic,
// writes sorted segment top-64 to g_seg.
// ---------------------------------------------------------------------------
__global__ __launch_bounds__(256)
void seg_select_kernel(int M) {
    const int seg = blockIdx.x;
    const int q   = blockIdx.y;
    const int tid = threadIdx.x;
    const int seg_len   = (M + NSEG - 1) / NSEG;
    const int seg_start = seg * seg_len;
    const int seg_end   = min(M, seg_start + seg_len);
    const float* row = g_score + (size_t)q * M;

    float ls[8]; int li[8];
#pragma unroll
    for (int j = 0; j < 8; j++) { ls[j] = FLT_MAX; li[j] = INT_MAX; }
    float worst = FLT_MAX;
#pragma unroll 4
    for (int m = seg_start + tid; m < seg_end; m += 256) {
        float s = row[m];
        if (s < worst) {
            float cs = s; int ci = m;
#pragma unroll
            for (int j = 0; j < 8; j++) {
                if (cs < ls[j] || (cs == ls[j] && ci < li[j])) {
                    float ts = ls[j]; ls[j] = cs; cs = ts;
                    int   ti = li[j]; li[j] = ci; ci = ti;
                }
            }
            worst = ls[7];
        }
    }

    __shared__ unsigned long long keys[2048];
#pragma unroll
    for (int j = 0; j < 8; j++)
        keys[tid * 8 + j] = pack_key(ls[j], li[j]);
    __syncthreads();

    for (int k = 2; k <= 2048; k <<= 1) {
        for (int j = k >> 1; j > 0; j >>= 1) {
            for (int t = tid; t < 2048; t += 256) {
                int ixj = t ^ j;
                if (ixj > t) {
                    unsigned long long a = keys[t], b = keys[ixj];
                    bool up = ((t & k) == 0);
                    if ((a > b) == up) { keys[t] = b; keys[ixj] = a; }
                }
            }
            __syncthreads();
        }
    }
    if (tid < NCAND)
        g_seg[((size_t)q * NSEG + seg) * NCAND + tid] = keys[tid];
}

// ---------------------------------------------------------------------------
// Kernel 3b: merge NSEG*64 = 1024 keys per query -> top-64 candidates.
// ---------------------------------------------------------------------------
__global__ __launch_bounds__(256)
void merge_cand_kernel() {
    const int q   = blockIdx.x;
    const int tid = threadIdx.x;
    __shared__ unsigned long long keys[NSEG * NCAND];   // 1024

    for (int t = tid; t < NSEG * NCAND; t += 256)
        keys[t] = g_seg[(size_t)q * NSEG * NCAND + t];
    __syncthreads();

    for (int k = 2; k <= NSEG * NCAND; k <<= 1) {
        for (int j = k >> 1; j > 0; j >>= 1) {
            for (int t = tid; t < NSEG * NCAND; t += 256) {
                int ixj = t ^ j;
                if (ixj > t) {
                    unsigned long long a = keys[t], b = keys[ixj];
                    bool up = ((t & k) == 0);
                    if ((a > b) == up) { keys[t] = b; keys[ixj] = a; }
                }
            }
            __syncthreads();
        }
    }
    if (tid < NCAND)
        g_cand[q * NCAND + tid] = (int)(keys[tid] & 0xffffffffu);
}

// ---------------------------------------------------------------------------
// Kernel 4: exact fp32 rescore of 64 candidates, top-16, gather trajectories.
// ---------------------------------------------------------------------------
__global__ __launch_bounds__(256)
void rescore_gather_kernel(const float* __restrict__ Q,
                           const float* __restrict__ Bank,
                           const float* __restrict__ traj,
                           float* __restrict__ out, int TD) {
    const int q   = blockIdx.x;
    const int tid = threadIdx.x;
    const int wid = tid >> 5, lane = tid & 31;

    __shared__ __align__(16) float qrow[C_DIM];
    __shared__ float cs[NCAND];
    __shared__ int   ci[NCAND];
    __shared__ unsigned long long k64[NCAND];

    for (int t = tid; t < C_DIM; t += 256)
        qrow[t] = Q[(size_t)q * C_DIM + t];
    __syncthreads();

    const float4* q4 = reinterpret_cast<const float4*>(qrow);
    for (int cand = wid; cand < NCAND; cand += 8) {
        int idx = g_cand[q * NCAND + cand];
        const float4* b4 = reinterpret_cast<const float4*>(Bank + (size_t)idx * C_DIM);
        float acc = 0.f;
#pragma unroll
        for (int j = lane; j < C_DIM / 4; j += 32) {
            float4 a = q4[j], b = b4[j];
            acc += a.x * b.x + a.y * b.y + a.z * b.z + a.w * b.w;
        }
#pragma unroll
        for (int off = 16; off > 0; off >>= 1)
            acc += __shfl_xor_sync(0xffffffffu, acc, off);
        if (lane == 0) { cs[cand] = g_bsq[idx] - 2.0f * acc; ci[cand] = idx; }
    }
    __syncthreads();

    if (tid < NCAND) k64[tid] = pack_key(cs[tid], ci[tid]);
    __syncthreads();
    for (int k = 2; k <= NCAND; k <<= 1) {
        for (int j = k >> 1; j > 0; j >>= 1) {
            for (int t = tid; t < NCAND; t += 256) {
                int ixj = t ^ j;
                if (ixj > t) {
                    unsigned long long a = k64[t], b = k64[ixj];
                    bool up = ((t & k) == 0);
                    if ((a > b) == up) { k64[t] = b; k64[ixj] = a; }
                }
            }
            __syncthreads();
        }
    }

    for (int t = tid; t < KSEL * TD; t += 256) {
        int r = t / TD;
        int c = t - r * TD;
        int idx = (int)(k64[r] & 0xffffffffu);
        out[(size_t)q * KSEL * TD + t] = traj[(size_t)idx * TD + c];
    }
}

// ---------------------------------------------------------------------------
// Launch
// ---------------------------------------------------------------------------
extern "C" void kernel_launch(void* const* d_in, const int* in_sizes, int n_in,
                              void* d_out, int out_size) {
    const float* Q    = (const float*)d_in[0];
    const float* Bank = (const float*)d_in[1];
    const float* Traj = (const float*)d_in[2];
    float* out = (float*)d_out;

    const int C  = C_DIM;
    const int B  = in_sizes[0] / C;    // 256
    const int M  = in_sizes[1] / C;    // 200000
    const int TD = in_sizes[2] / M;    // 24

    cudaFuncSetAttribute(mma_gemm_kernel,
                         cudaFuncAttributeMaxDynamicSharedMemorySize, GEMM_SMEM);

    float* bsq_p = nullptr;
    __nv_bfloat16 *bankbf_p = nullptr, *qbf_p = nullptr;
    cudaGetSymbolAddress((void**)&bsq_p, g_bsq);
    cudaGetSymbolAddress((void**)&bankbf_p, g_bank_bf);
    cudaGetSymbolAddress((void**)&qbf_p, g_q_bf);

    // 1) convert bank (+bsq) and query to bf16
    {
        int ctas = (M * 32 + 255) / 256;
        convert_kernel<<<ctas, 256>>>(Bank, bankbf_p, bsq_p, M);
        int qctas = (B * 32 + 255) / 256;
        convert_kernel<<<qctas, 256>>>(Q, qbf_p, nullptr, B);
    }
    // 2) coarse bf16 mma GEMM
    {
        dim3 grid(B / BM, (M + BN - 1) / BN);
        mma_gemm_kernel<<<grid, 256, GEMM_SMEM>>>(M);
    }
    // 3a) segmented coarse top-64
    {
        dim3 grid(NSEG, B);
        seg_select_kernel<<<grid, 256>>>(M);
    }
    // 3b) merge per-query candidates
    merge_cand_kernel<<<B, 256>>>();
    // 4) exact fp32 rescore + top-16 + gather
    rescore_gather_kernel<<<B, 256>>>(Q, Bank, Traj, out, TD);
}

// round 8
// speedup vs baseline: 1.9868x; 1.9868x over previous
#include <cuda_runtime.h>
#include <cuda_bf16.h>
#include <cfloat>
#include <climits>
#include <cstdint>

// ---------------------------------------------------------------------------
// Problem shape (fixed):
//   query [B=256,1024] f32, bank [M=200000,1024] f32, traj [M,8,3] f32, k=16
// Output: traj[nn_idx] sorted by ascending L2 dist, ties -> lower index.
// Pipeline: bf16 mma.sync coarse scores -> warp-level top-8 per subsegment
// (shuffle argmin, no block syncs) -> per-query merge to top-64 candidates
// -> exact fp32 rescore -> top-16 -> gather.
// ---------------------------------------------------------------------------

#define C_DIM   1024
#define B_MAX   256
#define M_MAX   200000
#define KSEL    16
#define NCAND   64
#define SEGC    32                  // CTAs per query in stage A
#define NSUB    (SEGC * 8)          // 256 warp-subsegments per query
#define WOUT    8                   // keys emitted per warp

// __device__ scratch (allocation-free rule)
__device__ __align__(16) float          g_score[(size_t)B_MAX * M_MAX];
__device__ __align__(16) float          g_bsq[M_MAX];
__device__ __align__(16) __nv_bfloat16  g_bank_bf[(size_t)M_MAX * C_DIM];
__device__ __align__(16) __nv_bfloat16  g_q_bf[(size_t)B_MAX * C_DIM];
__device__ __align__(16) unsigned long long g_seg[(size_t)B_MAX * NSUB * WOUT];
__device__                int           g_cand[B_MAX * NCAND];

#define SMEM_SWIZZLE_128B(o) ((o) ^ (((o) >> 3) & 0x70))

__device__ __forceinline__ uint32_t smem_to_u32(const void* p) {
    uint32_t a;
    asm("{ .reg .u64 t; cvta.to.shared.u64 t, %1; cvt.u32.u64 %0, t; }"
        : "=r"(a) : "l"(p));
    return a;
}
__device__ __forceinline__ void cp_async16(uint32_t dst, const void* src, int srcsize) {
    asm volatile("cp.async.cg.shared.global [%0], [%1], 16, %2;"
                 :: "r"(dst), "l"(src), "r"(srcsize));
}
__device__ __forceinline__ void cp_commit() {
    asm volatile("cp.async.commit_group;");
}
template <int N>
__device__ __forceinline__ void cp_wait() {
    asm volatile("cp.async.wait_group %0;" :: "n"(N));
}
__device__ __forceinline__ void ldmx4(uint32_t& r0, uint32_t& r1,
                                      uint32_t& r2, uint32_t& r3, uint32_t addr) {
    asm volatile("ldmatrix.sync.aligned.m8n8.x4.shared.b16 {%0,%1,%2,%3}, [%4];"
                 : "=r"(r0), "=r"(r1), "=r"(r2), "=r"(r3) : "r"(addr));
}
__device__ __forceinline__ void mma16816(float* c, const uint32_t* a, const uint32_t* b) {
    asm volatile(
        "mma.sync.aligned.m16n8k16.row.col.f32.bf16.bf16.f32 "
        "{%0,%1,%2,%3}, {%4,%5,%6,%7}, {%8,%9}, {%0,%1,%2,%3};"
        : "+f"(c[0]), "+f"(c[1]), "+f"(c[2]), "+f"(c[3])
        : "r"(a[0]), "r"(a[1]), "r"(a[2]), "r"(a[3]), "r"(b[0]), "r"(b[1]));
}

// ---------------------------------------------------------------------------
// Kernel 1: fp32 -> bf16 convert, fused squared norms. One warp per row.
// ---------------------------------------------------------------------------
__global__ void convert_kernel(const float* __restrict__ src,
                               __nv_bfloat16* __restrict__ dst,
                               float* __restrict__ bsq, int rows) {
    int warp = (blockIdx.x * blockDim.x + threadIdx.x) >> 5;
    int lane = threadIdx.x & 31;
    if (warp >= rows) return;
    const float4* srow = reinterpret_cast<const float4*>(src + (size_t)warp * C_DIM);
    __nv_bfloat162* drow = reinterpret_cast<__nv_bfloat162*>(dst + (size_t)warp * C_DIM);
    float acc = 0.f;
#pragma unroll
    for (int i = 0; i < C_DIM / 128; i++) {
        int j = i * 32 + lane;
        float4 v = srow[j];
        acc += v.x * v.x + v.y * v.y + v.z * v.z + v.w * v.w;
        drow[2 * j]     = __nv_bfloat162(__float2bfloat16(v.x), __float2bfloat16(v.y));
        drow[2 * j + 1] = __nv_bfloat162(__float2bfloat16(v.z), __float2bfloat16(v.w));
    }
    if (bsq) {
#pragma unroll
        for (int off = 16; off > 0; off >>= 1)
            acc += __shfl_xor_sync(0xffffffffu, acc, off);
        if (lane == 0) bsq[warp] = acc;
    }
}

// ---------------------------------------------------------------------------
// Kernel 2: coarse bf16 GEMM via mma.sync.m16n8k16. (unchanged, proven)
// ---------------------------------------------------------------------------
#define BM   128
#define BN   128
#define BKC  64
#define NCH  (C_DIM / BKC)
#define TILE_BYTES (BM * 128)
#define GEMM_SMEM  (4 * TILE_BYTES)

__global__ __launch_bounds__(256, 2)
void mma_gemm_kernel(int M) {
    extern __shared__ char smem[];
    const uint32_t sb = smem_to_u32(smem);
    const int tid  = threadIdx.x;
    const int wid  = tid >> 5;
    const int lane = tid & 31;
    const int qt = blockIdx.x;
    const int bn = blockIdx.y * BN;
    const int warp_m = wid & 1;
    const int warp_n = wid >> 1;

    const __nv_bfloat16* Abase = g_q_bf + (size_t)qt * BM * C_DIM;

    int lrow[4], lu[4];
#pragma unroll
    for (int l = 0; l < 4; l++) {
        int id = tid + l * 256;
        lrow[l] = id >> 3;
        lu[l]   = id & 7;
    }

    auto issue_loads = [&](int c, int buf) {
        int k0 = c * BKC;
        uint32_t As = sb + buf * 2 * TILE_BYTES;
        uint32_t Bs = As + TILE_BYTES;
#pragma unroll
        for (int l = 0; l < 4; l++) {
            uint32_t so = SMEM_SWIZZLE_128B((uint32_t)(lrow[l] * 128 + lu[l] * 16));
            cp_async16(As + so, Abase + (size_t)lrow[l] * C_DIM + k0 + lu[l] * 8, 16);
            int n = bn + lrow[l];
            const void* srcB = g_bank_bf + (size_t)(n < M ? n : 0) * C_DIM + k0 + lu[l] * 8;
            cp_async16(Bs + so, srcB, n < M ? 16 : 0);
        }
        cp_commit();
    };

    float acc[4][4][4];
#pragma unroll
    for (int mi = 0; mi < 4; mi++)
#pragma unroll
        for (int nj = 0; nj < 4; nj++)
#pragma unroll
            for (int e = 0; e < 4; e++) acc[mi][nj][e] = 0.f;

    issue_loads(0, 0);

    for (int c = 0; c < NCH; c++) {
        int buf = c & 1;
        if (c + 1 < NCH) {
            issue_loads(c + 1, buf ^ 1);
            cp_wait<1>();
        } else {
            cp_wait<0>();
        }
        __syncthreads();

        uint32_t As = sb + buf * 2 * TILE_BYTES;
        uint32_t Bs = As + TILE_BYTES;
#pragma unroll
        for (int ks = 0; ks < BKC / 16; ks++) {
            uint32_t a[4][4];
            int arow = warp_m * 64 + (lane & 15);
            int akb  = ks * 16 + (lane >> 4) * 8;
#pragma unroll
            for (int mi = 0; mi < 4; mi++) {
                uint32_t so = SMEM_SWIZZLE_128B(
                    (uint32_t)((arow + mi * 16) * 128 + akb * 2));
                ldmx4(a[mi][0], a[mi][1], a[mi][2], a[mi][3], As + so);
            }
            uint32_t b[4][2];
            int g = lane >> 3;
#pragma unroll
            for (int pair = 0; pair < 2; pair++) {
                int brow = warp_n * 32 + pair * 16 + ((g >> 1) & 1) * 8 + (lane & 7);
                int bkb  = ks * 16 + (g & 1) * 8;
                uint32_t so = SMEM_SWIZZLE_128B((uint32_t)(brow * 128 + bkb * 2));
                uint32_t r0, r1, r2, r3;
                ldmx4(r0, r1, r2, r3, Bs + so);
                b[2 * pair][0] = r0; b[2 * pair][1] = r1;
                b[2 * pair + 1][0] = r2; b[2 * pair + 1][1] = r3;
            }
#pragma unroll
            for (int mi = 0; mi < 4; mi++)
#pragma unroll
                for (int nj = 0; nj < 4; nj++)
                    mma16816(acc[mi][nj], a[mi], b[nj]);
        }
        __syncthreads();
    }

    const int qbase = qt * BM + warp_m * 64;
    const int nbase = bn + warp_n * 32;
#pragma unroll
    for (int mi = 0; mi < 4; mi++) {
#pragma unroll
        for (int nj = 0; nj < 4; nj++) {
            int n0 = nbase + nj * 8 + (lane & 3) * 2;
            if (n0 + 1 < M) {
                float b0 = g_bsq[n0], b1 = g_bsq[n0 + 1];
                int q0 = qbase + mi * 16 + (lane >> 2);
                float2 v0 = make_float2(b0 - 2.f * acc[mi][nj][0],
                                        b1 - 2.f * acc[mi][nj][1]);
                float2 v1 = make_float2(b0 - 2.f * acc[mi][nj][2],
                                        b1 - 2.f * acc[mi][nj][3]);
                *reinterpret_cast<float2*>(g_score + (size_t)q0 * M + n0) = v0;
                *reinterpret_cast<float2*>(g_score + (size_t)(q0 + 8) * M + n0) = v1;
            } else if (n0 < M) {
                float b0 = g_bsq[n0];
                int q0 = qbase + mi * 16 + (lane >> 2);
                g_score[(size_t)q0 * M + n0]       = b0 - 2.f * acc[mi][nj][0];
                g_score[(size_t)(q0 + 8) * M + n0] = b0 - 2.f * acc[mi][nj][2];
            }
        }
    }
}

// ---------------------------------------------------------------------------
// Selection helpers
// ---------------------------------------------------------------------------
__device__ __forceinline__ unsigned long long pack_key(float s, int idx) {
    unsigned u = __float_as_uint(s);
    u = (u & 0x80000000u) ? ~u : (u | 0x80000000u);
    return ((unsigned long long)u << 32) | (unsigned)idx;
}
__device__ __forceinline__ unsigned long long warp_min_ull(unsigned long long v) {
#pragma unroll
    for (int off = 16; off > 0; off >>= 1) {
        unsigned long long o = __shfl_xor_sync(0xffffffffu, v, off);
        v = (o < v) ? o : v;
    }
    return v;
}

// ---------------------------------------------------------------------------
// Kernel 3a: warp-level subsegment top-8. grid = (SEGC, B), 8 warps/CTA.
// Each warp scans M/NSUB elements; lanes keep sorted top-8; 8 shuffle-argmin
// rounds emit the warp's exact top-8 keys. No block-level syncs.
// ---------------------------------------------------------------------------
__global__ __launch_bounds__(256)
void warp_select_kernel(int M) {
    const int q    = blockIdx.y;
    const int wid  = threadIdx.x >> 5;
    const int lane = threadIdx.x & 31;
    const int sub  = blockIdx.x * 8 + wid;           // 0..NSUB-1
    const int sub_len = (M + NSUB - 1) / NSUB;
    const int start   = sub * sub_len;
    const int end     = min(M, start + sub_len);
    const float* row  = g_score + (size_t)q * M;

    float ls[8]; int li[8];
#pragma unroll
    for (int j = 0; j < 8; j++) { ls[j] = FLT_MAX; li[j] = INT_MAX; }
    float worst = FLT_MAX;
    for (int m = start + lane; m < end; m += 32) {
        float s = row[m];
        if (s < worst) {
            float cs = s; int ci = m;
#pragma unroll
            for (int j = 0; j < 8; j++) {
                if (cs < ls[j] || (cs == ls[j] && ci < li[j])) {
                    float ts = ls[j]; ls[j] = cs; cs = ts;
                    int   ti = li[j]; li[j] = ci; ci = ti;
                }
            }
            worst = ls[7];
        }
    }

    unsigned long long kk[8];
#pragma unroll
    for (int j = 0; j < 8; j++) kk[j] = pack_key(ls[j], li[j]);

    unsigned long long mine = ~0ull;
#pragma unroll
    for (int r = 0; r < WOUT; r++) {
        unsigned long long best = warp_min_ull(kk[0]);
        if (kk[0] == best) {                 // unique: key embeds index
#pragma unroll
            for (int j = 0; j < 7; j++) kk[j] = kk[j + 1];
            kk[7] = ~0ull;
        }
        if (lane == r) mine = best;
    }
    if (lane < WOUT)
        g_seg[((size_t)q * NSUB + sub) * WOUT + lane] = mine;
}

// ---------------------------------------------------------------------------
// Kernel 3b: merge 2048 stage-A keys per query -> top-64 candidate set.
// 8 warps x (256 keys -> warp top-32 via shuffles), then 256-key bitonic.
// ---------------------------------------------------------------------------
__global__ __launch_bounds__(256)
void merge_cand_kernel() {
    const int q    = blockIdx.x;
    const int tid  = threadIdx.x;
    const int wid  = tid >> 5;
    const int lane = tid & 31;
    __shared__ unsigned long long keys[256];

    // each lane owns one subsegment's 8 sorted keys (already sorted by 3a)
    unsigned long long kk[8];
    const unsigned long long* src =
        g_seg + (size_t)q * NSUB * WOUT + (size_t)(wid * 32 + lane) * WOUT;
#pragma unroll
    for (int j = 0; j < 8; j++) kk[j] = src[j];

    // warp top-32 of its 256 keys (exact; lanes' lists are sorted)
    unsigned long long mine = ~0ull;
#pragma unroll
    for (int r = 0; r < 32; r++) {
        unsigned long long best = warp_min_ull(kk[0]);
        if (kk[0] == best) {
#pragma unroll
            for (int j = 0; j < 7; j++) kk[j] = kk[j + 1];
            kk[7] = ~0ull;
        }
        if (lane == r) mine = best;
    }
    keys[wid * 32 + lane] = mine;
    __syncthreads();

    // bitonic sort 256 keys, 1 per thread
    for (int k = 2; k <= 256; k <<= 1) {
        for (int j = k >> 1; j > 0; j >>= 1) {
            int ixj = tid ^ j;
            if (ixj > tid) {
                unsigned long long a = keys[tid], b = keys[ixj];
                bool up = ((tid & k) == 0);
                if ((a > b) == up) { keys[tid] = b; keys[ixj] = a; }
            }
            __syncthreads();
        }
    }
    if (tid < NCAND)
        g_cand[q * NCAND + tid] = (int)(keys[tid] & 0xffffffffu);
}

// ---------------------------------------------------------------------------
// Kernel 4: exact fp32 rescore of 64 candidates, top-16, gather trajectories.
// ---------------------------------------------------------------------------
__global__ __launch_bounds__(256)
void rescore_gather_kernel(const float* __restrict__ Q,
                           const float* __restrict__ Bank,
                           const float* __restrict__ traj,
                           float* __restrict__ out, int TD) {
    const int q   = blockIdx.x;
    const int tid = threadIdx.x;
    const int wid = tid >> 5, lane = tid & 31;

    __shared__ __align__(16) float qrow[C_DIM];
    __shared__ float cs[NCAND];
    __shared__ int   ci[NCAND];
    __shared__ unsigned long long k64[NCAND];

    for (int t = tid; t < C_DIM; t += 256)
        qrow[t] = Q[(size_t)q * C_DIM + t];
    __syncthreads();

    const float4* q4 = reinterpret_cast<const float4*>(qrow);
    for (int cand = wid; cand < NCAND; cand += 8) {
        int idx = g_cand[q * NCAND + cand];
        const float4* b4 = reinterpret_cast<const float4*>(Bank + (size_t)idx * C_DIM);
        float acc = 0.f;
#pragma unroll
        for (int j = lane; j < C_DIM / 4; j += 32) {
            float4 a = q4[j], b = b4[j];
            acc += a.x * b.x + a.y * b.y + a.z * b.z + a.w * b.w;
        }
#pragma unroll
        for (int off = 16; off > 0; off >>= 1)
            acc += __shfl_xor_sync(0xffffffffu, acc, off);
        if (lane == 0) { cs[cand] = g_bsq[idx] - 2.0f * acc; ci[cand] = idx; }
    }
    __syncthreads();

    if (tid < NCAND) k64[tid] = pack_key(cs[tid], ci[tid]);
    __syncthreads();
    for (int k = 2; k <= NCAND; k <<= 1) {
        for (int j = k >> 1; j > 0; j >>= 1) {
            for (int t = tid; t < NCAND; t += 256) {
                int ixj = t ^ j;
                if (ixj > t) {
                    unsigned long long a = k64[t], b = k64[ixj];
                    bool up = ((t & k) == 0);
                    if ((a > b) == up) { k64[t] = b; k64[ixj] = a; }
                }
            }
            __syncthreads();
        }
    }

    for (int t = tid; t < KSEL * TD; t += 256) {
        int r = t / TD;
        int c = t - r * TD;
        int idx = (int)(k64[r] & 0xffffffffu);
        out[(size_t)q * KSEL * TD + t] = traj[(size_t)idx * TD + c];
    }
}

// ---------------------------------------------------------------------------
// Launch
// ---------------------------------------------------------------------------
extern "C" void kernel_launch(void* const* d_in, const int* in_sizes, int n_in,
                              void* d_out, int out_size) {
    const float* Q    = (const float*)d_in[0];
    const float* Bank = (const float*)d_in[1];
    const float* Traj = (const float*)d_in[2];
    float* out = (float*)d_out;

    const int C  = C_DIM;
    const int B  = in_sizes[0] / C;    // 256
    const int M  = in_sizes[1] / C;    // 200000
    const int TD = in_sizes[2] / M;    // 24

    cudaFuncSetAttribute(mma_gemm_kernel,
                         cudaFuncAttributeMaxDynamicSharedMemorySize, GEMM_SMEM);

    float* bsq_p = nullptr;
    __nv_bfloat16 *bankbf_p = nullptr, *qbf_p = nullptr;
    cudaGetSymbolAddress((void**)&bsq_p, g_bsq);
    cudaGetSymbolAddress((void**)&bankbf_p, g_bank_bf);
    cudaGetSymbolAddress((void**)&qbf_p, g_q_bf);

    // 1) convert bank (+bsq) and query to bf16
    {
        int ctas = (M * 32 + 255) / 256;
        convert_kernel<<<ctas, 256>>>(Bank, bankbf_p, bsq_p, M);
        int qctas = (B * 32 + 255) / 256;
        convert_kernel<<<qctas, 256>>>(Q, qbf_p, nullptr, B);
    }
    // 2) coarse bf16 mma GEMM
    {
        dim3 grid(B / BM, (M + BN - 1) / BN);
        mma_gemm_kernel<<<grid, 256, GEMM_SMEM>>>(M);
    }
    // 3a) warp-level subsegment top-8
    {
        dim3 grid(SEGC, B);
        warp_select_kernel<<<grid, 256>>>(M);
    }
    // 3b) merge per-query candidates
    merge_cand_kernel<<<B, 256>>>();
    // 4) exact fp32 rescore + top-16 + gather
    rescore_gather_kernel<<<B, 256>>>(Q, Bank, Traj, out, TD);
}

// round 11
// speedup vs baseline: 2.1657x; 1.0900x over previous
#include <cuda_runtime.h>
#include <cuda_bf16.h>
#include <cfloat>
#include <climits>
#include <cstdint>

// ---------------------------------------------------------------------------
// Problem shape (fixed):
//   query [B=256,1024] f32, bank [M=200000,1024] f32, traj [M,8,3] f32, k=16
// Output: traj[nn_idx] sorted by ascending L2 dist, ties -> lower index.
// Pipeline: bf16 mma.sync coarse scores -> warp-level top-8 per subsegment
// (float4 scan + shuffle argmin) -> per-query merge to top-64 candidates
// -> exact fp32 rescore -> top-16 -> gather.
// ---------------------------------------------------------------------------

#define C_DIM   1024
#define B_MAX   256
#define M_MAX   200000
#define KSEL    16
#define NCAND   64
#define SEGC    32                  // CTAs per query in stage A
#define NSUB    (SEGC * 8)          // 256 warp-subsegments per query
#define WOUT    8                   // keys emitted per warp

// __device__ scratch (allocation-free rule)
__device__ __align__(16) float          g_score[(size_t)B_MAX * M_MAX];
__device__ __align__(16) float          g_bsq[M_MAX];
__device__ __align__(16) __nv_bfloat16  g_bank_bf[(size_t)M_MAX * C_DIM];
__device__ __align__(16) __nv_bfloat16  g_q_bf[(size_t)B_MAX * C_DIM];
__device__ __align__(16) unsigned long long g_seg[(size_t)B_MAX * NSUB * WOUT];
__device__                int           g_cand[B_MAX * NCAND];

#define SMEM_SWIZZLE_128B(o) ((o) ^ (((o) >> 3) & 0x70))

__device__ __forceinline__ uint32_t smem_to_u32(const void* p) {
    uint32_t a;
    asm("{ .reg .u64 t; cvta.to.shared.u64 t, %1; cvt.u32.u64 %0, t; }"
        : "=r"(a) : "l"(p));
    return a;
}
__device__ __forceinline__ void cp_async16(uint32_t dst, const void* src, int srcsize) {
    asm volatile("cp.async.cg.shared.global [%0], [%1], 16, %2;"
                 :: "r"(dst), "l"(src), "r"(srcsize));
}
__device__ __forceinline__ void cp_commit() {
    asm volatile("cp.async.commit_group;");
}
template <int N>
__device__ __forceinline__ void cp_wait() {
    asm volatile("cp.async.wait_group %0;" :: "n"(N));
}
__device__ __forceinline__ void ldmx4(uint32_t& r0, uint32_t& r1,
                                      uint32_t& r2, uint32_t& r3, uint32_t addr) {
    asm volatile("ldmatrix.sync.aligned.m8n8.x4.shared.b16 {%0,%1,%2,%3}, [%4];"
                 : "=r"(r0), "=r"(r1), "=r"(r2), "=r"(r3) : "r"(addr));
}
__device__ __forceinline__ void mma16816(float* c, const uint32_t* a, const uint32_t* b) {
    asm volatile(
        "mma.sync.aligned.m16n8k16.row.col.f32.bf16.bf16.f32 "
        "{%0,%1,%2,%3}, {%4,%5,%6,%7}, {%8,%9}, {%0,%1,%2,%3};"
        : "+f"(c[0]), "+f"(c[1]), "+f"(c[2]), "+f"(c[3])
        : "r"(a[0]), "r"(a[1]), "r"(a[2]), "r"(a[3]), "r"(b[0]), "r"(b[1]));
}

// ---------------------------------------------------------------------------
// Kernel 1: fp32 -> bf16 convert, fused squared norms. One warp per row.
// ---------------------------------------------------------------------------
__global__ void convert_kernel(const float* __restrict__ src,
                               __nv_bfloat16* __restrict__ dst,
                               float* __restrict__ bsq, int rows) {
    int warp = (blockIdx.x * blockDim.x + threadIdx.x) >> 5;
    int lane = threadIdx.x & 31;
    if (warp >= rows) return;
    const float4* srow = reinterpret_cast<const float4*>(src + (size_t)warp * C_DIM);
    __nv_bfloat162* drow = reinterpret_cast<__nv_bfloat162*>(dst + (size_t)warp * C_DIM);
    float acc = 0.f;
#pragma unroll
    for (int i = 0; i < C_DIM / 128; i++) {
        int j = i * 32 + lane;
        float4 v = srow[j];
        acc += v.x * v.x + v.y * v.y + v.z * v.z + v.w * v.w;
        drow[2 * j]     = __nv_bfloat162(__float2bfloat16(v.x), __float2bfloat16(v.y));
        drow[2 * j + 1] = __nv_bfloat162(__float2bfloat16(v.z), __float2bfloat16(v.w));
    }
    if (bsq) {
#pragma unroll
        for (int off = 16; off > 0; off >>= 1)
            acc += __shfl_xor_sync(0xffffffffu, acc, off);
        if (lane == 0) bsq[warp] = acc;
    }
}

// ---------------------------------------------------------------------------
// Kernel 2: coarse bf16 GEMM via mma.sync.m16n8k16. (unchanged, proven)
// ---------------------------------------------------------------------------
#define BM   128
#define BN   128
#define BKC  64
#define NCH  (C_DIM / BKC)
#define TILE_BYTES (BM * 128)
#define GEMM_SMEM  (4 * TILE_BYTES)

__global__ __launch_bounds__(256, 2)
void mma_gemm_kernel(int M) {
    extern __shared__ char smem[];
    const uint32_t sb = smem_to_u32(smem);
    const int tid  = threadIdx.x;
    const int wid  = tid >> 5;
    const int lane = tid & 31;
    const int qt = blockIdx.x;
    const int bn = blockIdx.y * BN;
    const int warp_m = wid & 1;
    const int warp_n = wid >> 1;

    const __nv_bfloat16* Abase = g_q_bf + (size_t)qt * BM * C_DIM;

    int lrow[4], lu[4];
#pragma unroll
    for (int l = 0; l < 4; l++) {
        int id = tid + l * 256;
        lrow[l] = id >> 3;
        lu[l]   = id & 7;
    }

    auto issue_loads = [&](int c, int buf) {
        int k0 = c * BKC;
        uint32_t As = sb + buf * 2 * TILE_BYTES;
        uint32_t Bs = As + TILE_BYTES;
#pragma unroll
        for (int l = 0; l < 4; l++) {
            uint32_t so = SMEM_SWIZZLE_128B((uint32_t)(lrow[l] * 128 + lu[l] * 16));
            cp_async16(As + so, Abase + (size_t)lrow[l] * C_DIM + k0 + lu[l] * 8, 16);
            int n = bn + lrow[l];
            const void* srcB = g_bank_bf + (size_t)(n < M ? n : 0) * C_DIM + k0 + lu[l] * 8;
            cp_async16(Bs + so, srcB, n < M ? 16 : 0);
        }
        cp_commit();
    };

    float acc[4][4][4];
#pragma unroll
    for (int mi = 0; mi < 4; mi++)
#pragma unroll
        for (int nj = 0; nj < 4; nj++)
#pragma unroll
            for (int e = 0; e < 4; e++) acc[mi][nj][e] = 0.f;

    issue_loads(0, 0);

    for (int c = 0; c < NCH; c++) {
        int buf = c & 1;
        if (c + 1 < NCH) {
            issue_loads(c + 1, buf ^ 1);
            cp_wait<1>();
        } else {
            cp_wait<0>();
        }
        __syncthreads();

        uint32_t As = sb + buf * 2 * TILE_BYTES;
        uint32_t Bs = As + TILE_BYTES;
#pragma unroll
        for (int ks = 0; ks < BKC / 16; ks++) {
            uint32_t a[4][4];
            int arow = warp_m * 64 + (lane & 15);
            int akb  = ks * 16 + (lane >> 4) * 8;
#pragma unroll
            for (int mi = 0; mi < 4; mi++) {
                uint32_t so = SMEM_SWIZZLE_128B(
                    (uint32_t)((arow + mi * 16) * 128 + akb * 2));
                ldmx4(a[mi][0], a[mi][1], a[mi][2], a[mi][3], As + so);
            }
            uint32_t b[4][2];
            int g = lane >> 3;
#pragma unroll
            for (int pair = 0; pair < 2; pair++) {
                int brow = warp_n * 32 + pair * 16 + ((g >> 1) & 1) * 8 + (lane & 7);
                int bkb  = ks * 16 + (g & 1) * 8;
                uint32_t so = SMEM_SWIZZLE_128B((uint32_t)(brow * 128 + bkb * 2));
                uint32_t r0, r1, r2, r3;
                ldmx4(r0, r1, r2, r3, Bs + so);
                b[2 * pair][0] = r0; b[2 * pair][1] = r1;
                b[2 * pair + 1][0] = r2; b[2 * pair + 1][1] = r3;
            }
#pragma unroll
            for (int mi = 0; mi < 4; mi++)
#pragma unroll
                for (int nj = 0; nj < 4; nj++)
                    mma16816(acc[mi][nj], a[mi], b[nj]);
        }
        __syncthreads();
    }

    const int qbase = qt * BM + warp_m * 64;
    const int nbase = bn + warp_n * 32;
#pragma unroll
    for (int mi = 0; mi < 4; mi++) {
#pragma unroll
        for (int nj = 0; nj < 4; nj++) {
            int n0 = nbase + nj * 8 + (lane & 3) * 2;
            if (n0 + 1 < M) {
                float b0 = g_bsq[n0], b1 = g_bsq[n0 + 1];
                int q0 = qbase + mi * 16 + (lane >> 2);
                float2 v0 = make_float2(b0 - 2.f * acc[mi][nj][0],
                                        b1 - 2.f * acc[mi][nj][1]);
                float2 v1 = make_float2(b0 - 2.f * acc[mi][nj][2],
                                        b1 - 2.f * acc[mi][nj][3]);
                *reinterpret_cast<float2*>(g_score + (size_t)q0 * M + n0) = v0;
                *reinterpret_cast<float2*>(g_score + (size_t)(q0 + 8) * M + n0) = v1;
            } else if (n0 < M) {
                float b0 = g_bsq[n0];
                int q0 = qbase + mi * 16 + (lane >> 2);
                g_score[(size_t)q0 * M + n0]       = b0 - 2.f * acc[mi][nj][0];
                g_score[(size_t)(q0 + 8) * M + n0] = b0 - 2.f * acc[mi][nj][2];
            }
        }
    }
}

// ---------------------------------------------------------------------------
// Selection helpers
// ---------------------------------------------------------------------------
__device__ __forceinline__ unsigned long long pack_key(float s, int idx) {
    unsigned u = __float_as_uint(s);
    u = (u & 0x80000000u) ? ~u : (u | 0x80000000u);
    return ((unsigned long long)u << 32) | (unsigned)idx;
}
__device__ __forceinline__ unsigned long long warp_min_ull(unsigned long long v) {
#pragma unroll
    for (int off = 16; off > 0; off >>= 1) {
        unsigned long long o = __shfl_xor_sync(0xffffffffu, v, off);
        v = (o < v) ? o : v;
    }
    return v;
}

// ---------------------------------------------------------------------------
// Kernel 3a: warp-level subsegment top-8, float4 scan. grid = (SEGC, B).
// Subsegments are float4-granular: 196 float4 (784 floats) each, 256/query.
// Lanes keep sorted top-8; 8 shuffle-argmin rounds emit warp top-8 keys.
// ---------------------------------------------------------------------------
__global__ __launch_bounds__(256)
void warp_select_kernel(int M) {
    const int q    = blockIdx.y;
    const int wid  = threadIdx.x >> 5;
    const int lane = threadIdx.x & 31;
    const int sub  = blockIdx.x * 8 + wid;            // 0..NSUB-1
    const int M4   = M >> 2;                          // 50000 float4
    const int sub_len4 = (M4 + NSUB - 1) / NSUB;      // 196
    const int start4   = sub * sub_len4;
    const int end4     = min(M4, start4 + sub_len4);
    const float4* row4 = reinterpret_cast<const float4*>(g_score + (size_t)q * M);

    float ls[8]; int li[8];
#pragma unroll
    for (int j = 0; j < 8; j++) { ls[j] = FLT_MAX; li[j] = INT_MAX; }
    float worst = FLT_MAX;

    auto insert = [&](float s, int idx) {
        float cs = s; int ci = idx;
#pragma unroll
        for (int j = 0; j < 8; j++) {
            if (cs < ls[j] || (cs == ls[j] && ci < li[j])) {
                float ts = ls[j]; ls[j] = cs; cs = ts;
                int   ti = li[j]; li[j] = ci; ci = ti;
            }
        }
        worst = ls[7];
    };

    for (int j4 = start4 + lane; j4 < end4; j4 += 32) {
        float4 v = row4[j4];
        float mn = fminf(fminf(v.x, v.y), fminf(v.z, v.w));
        if (mn < worst) {
            int m = j4 * 4;
            if (v.x < worst) insert(v.x, m);
            if (v.y < worst) insert(v.y, m + 1);
            if (v.z < worst) insert(v.z, m + 2);
            if (v.w < worst) insert(v.w, m + 3);
        }
    }

    unsigned long long kk[8];
#pragma unroll
    for (int j = 0; j < 8; j++) kk[j] = pack_key(ls[j], li[j]);

    unsigned long long mine = ~0ull;
#pragma unroll
    for (int r = 0; r < WOUT; r++) {
        unsigned long long best = warp_min_ull(kk[0]);
        if (kk[0] == best) {                 // unique: key embeds index
#pragma unroll
            for (int j = 0; j < 7; j++) kk[j] = kk[j + 1];
            kk[7] = ~0ull;
        }
        if (lane == r) mine = best;
    }
    if (lane < WOUT)
        g_seg[((size_t)q * NSUB + sub) * WOUT + lane] = mine;
}

// ---------------------------------------------------------------------------
// Kernel 3b: merge 2048 stage-A keys per query -> top-64 candidate set.
// ---------------------------------------------------------------------------
__global__ __launch_bounds__(256)
void merge_cand_kernel() {
    const int q    = blockIdx.x;
    const int tid  = threadIdx.x;
    const int wid  = tid >> 5;
    const int lane = tid & 31;
    __shared__ unsigned long long keys[256];

    unsigned long long kk[8];
    const unsigned long long* src =
        g_seg + (size_t)q * NSUB * WOUT + (size_t)(wid * 32 + lane) * WOUT;
#pragma unroll
    for (int j = 0; j < 8; j++) kk[j] = src[j];

    unsigned long long mine = ~0ull;
#pragma unroll
    for (int r = 0; r < 32; r++) {
        unsigned long long best = warp_min_ull(kk[0]);
        if (kk[0] == best) {
#pragma unroll
            for (int j = 0; j < 7; j++) kk[j] = kk[j + 1];
            kk[7] = ~0ull;
        }
        if (lane == r) mine = best;
    }
    keys[wid * 32 + lane] = mine;
    __syncthreads();

    for (int k = 2; k <= 256; k <<= 1) {
        for (int j = k >> 1; j > 0; j >>= 1) {
            int ixj = tid ^ j;
            if (ixj > tid) {
                unsigned long long a = keys[tid], b = keys[ixj];
                bool up = ((tid & k) == 0);
                if ((a > b) == up) { keys[tid] = b; keys[ixj] = a; }
            }
            __syncthreads();
        }
    }
    if (tid < NCAND)
        g_cand[q * NCAND + tid] = (int)(keys[tid] & 0xffffffffu);
}

// ---------------------------------------------------------------------------
// Kernel 4: exact fp32 rescore of 64 candidates, top-16, gather trajectories.
// ---------------------------------------------------------------------------
__global__ __launch_bounds__(256)
void rescore_gather_kernel(const float* __restrict__ Q,
                           const float* __restrict__ Bank,
                           const float* __restrict__ traj,
                           float* __restrict__ out, int TD) {
    const int q   = blockIdx.x;
    const int tid = threadIdx.x;
    const int wid = tid >> 5, lane = tid & 31;

    __shared__ __align__(16) float qrow[C_DIM];
    __shared__ float cs[NCAND];
    __shared__ int   ci[NCAND];
    __shared__ unsigned long long k64[NCAND];

    for (int t = tid; t < C_DIM; t += 256)
        qrow[t] = Q[(size_t)q * C_DIM + t];
    __syncthreads();

    const float4* q4 = reinterpret_cast<const float4*>(qrow);
    for (int cand = wid; cand < NCAND; cand += 8) {
        int idx = g_cand[q * NCAND + cand];
        const float4* b4 = reinterpret_cast<const float4*>(Bank + (size_t)idx * C_DIM);
        float acc = 0.f;
#pragma unroll
        for (int j = lane; j < C_DIM / 4; j += 32) {
            float4 a = q4[j], b = b4[j];
            acc += a.x * b.x + a.y * b.y + a.z * b.z + a.w * b.w;
        }
#pragma unroll
        for (int off = 16; off > 0; off >>= 1)
            acc += __shfl_xor_sync(0xffffffffu, acc, off);
        if (lane == 0) { cs[cand] = g_bsq[idx] - 2.0f * acc; ci[cand] = idx; }
    }
    __syncthreads();

    if (tid < NCAND) k64[tid] = pack_key(cs[tid], ci[tid]);
    __syncthreads();
    for (int k = 2; k <= NCAND; k <<= 1) {
        for (int j = k >> 1; j > 0; j >>= 1) {
            for (int t = tid; t < NCAND; t += 256) {
                int ixj = t ^ j;
                if (ixj > t) {
                    unsigned long long a = k64[t], b = k64[ixj];
                    bool up = ((t & k) == 0);
                    if ((a > b) == up) { k64[t] = b; k64[ixj] = a; }
                }
            }
            __syncthreads();
        }
    }

    for (int t = tid; t < KSEL * TD; t += 256) {
        int r = t / TD;
        int c = t - r * TD;
        int idx = (int)(k64[r] & 0xffffffffu);
        out[(size_t)q * KSEL * TD + t] = traj[(size_t)idx * TD + c];
    }
}

// ---------------------------------------------------------------------------
// Launch
// ---------------------------------------------------------------------------
extern "C" void kernel_launch(void* const* d_in, const int* in_sizes, int n_in,
                              void* d_out, int out_size) {
    const float* Q    = (const float*)d_in[0];
    const float* Bank = (const float*)d_in[1];
    const float* Traj = (const float*)d_in[2];
    float* out = (float*)d_out;

    const int C  = C_DIM;
    const int B  = in_sizes[0] / C;    // 256
    const int M  = in_sizes[1] / C;    // 200000
    const int TD = in_sizes[2] / M;    // 24

    cudaFuncSetAttribute(mma_gemm_kernel,
                         cudaFuncAttributeMaxDynamicSharedMemorySize, GEMM_SMEM);

    float* bsq_p = nullptr;
    __nv_bfloat16 *bankbf_p = nullptr, *qbf_p = nullptr;
    cudaGetSymbolAddress((void**)&bsq_p, g_bsq);
    cudaGetSymbolAddress((void**)&bankbf_p, g_bank_bf);
    cudaGetSymbolAddress((void**)&qbf_p, g_q_bf);

    // 1) convert bank (+bsq) and query to bf16
    {
        int ctas = (M * 32 + 255) / 256;
        convert_kernel<<<ctas, 256>>>(Bank, bankbf_p, bsq_p, M);
        int qctas = (B * 32 + 255) / 256;
        convert_kernel<<<qctas, 256>>>(Q, qbf_p, nullptr, B);
    }
    // 2) coarse bf16 mma GEMM
    {
        dim3 grid(B / BM, (M + BN - 1) / BN);
        mma_gemm_kernel<<<grid, 256, GEMM_SMEM>>>(M);
    }
    // 3a) warp-level subsegment top-8 (float4 scan)
    {
        dim3 grid(SEGC, B);
        warp_select_kernel<<<grid, 256>>>(M);
    }
    // 3b) merge per-query candidates
    merge_cand_kernel<<<B, 256>>>();
    // 4) exact fp32 rescore + top-16 + gather
    rescore_gather_kernel<<<B, 256>>>(Q, Bank, Traj, out, TD);
}

// round 12
// speedup vs baseline: 2.6511x; 1.2241x over previous
#include <cuda_runtime.h>
#include <cuda_bf16.h>
#include <cfloat>
#include <climits>
#include <cstdint>

// ---------------------------------------------------------------------------
// Problem shape (fixed):
//   query [B=256,1024] f32, bank [M=200000,1024] f32, traj [M,8,3] f32, k=16
// Output: traj[nn_idx] sorted by ascending L2 dist, ties -> lower index.
// Pipeline: bf16 mma.sync coarse scores -> sample-threshold filter ->
// exact top-64 of surviving keys -> exact fp32 rescore -> top-16 -> gather.
// ---------------------------------------------------------------------------

#define C_DIM   1024
#define B_MAX   256
#define M_MAX   200000
#define KSEL    16
#define NCAND   64
#define CAP     4096                 // per-query filtered-key capacity
#define SAMPLE4 800                  // float4s sampled for threshold (3200 elems)
#define THR_RANK 8                   // take 8th smallest of sample

// __device__ scratch (allocation-free rule)
__device__ __align__(16) float          g_score[(size_t)B_MAX * M_MAX];
__device__ __align__(16) float          g_bsq[M_MAX];
__device__ __align__(16) __nv_bfloat16  g_bank_bf[(size_t)M_MAX * C_DIM];
__device__ __align__(16) __nv_bfloat16  g_q_bf[(size_t)B_MAX * C_DIM];
__device__ __align__(16) unsigned long long g_list[(size_t)B_MAX * CAP];
__device__                int           g_count[B_MAX];
__device__                float         g_thresh[B_MAX];
__device__                int           g_cand[B_MAX * NCAND];

#define SMEM_SWIZZLE_128B(o) ((o) ^ (((o) >> 3) & 0x70))

__device__ __forceinline__ uint32_t smem_to_u32(const void* p) {
    uint32_t a;
    asm("{ .reg .u64 t; cvta.to.shared.u64 t, %1; cvt.u32.u64 %0, t; }"
        : "=r"(a) : "l"(p));
    return a;
}
__device__ __forceinline__ void cp_async16(uint32_t dst, const void* src, int srcsize) {
    asm volatile("cp.async.cg.shared.global [%0], [%1], 16, %2;"
                 :: "r"(dst), "l"(src), "r"(srcsize));
}
__device__ __forceinline__ void cp_commit() {
    asm volatile("cp.async.commit_group;");
}
template <int N>
__device__ __forceinline__ void cp_wait() {
    asm volatile("cp.async.wait_group %0;" :: "n"(N));
}
__device__ __forceinline__ void ldmx4(uint32_t& r0, uint32_t& r1,
                                      uint32_t& r2, uint32_t& r3, uint32_t addr) {
    asm volatile("ldmatrix.sync.aligned.m8n8.x4.shared.b16 {%0,%1,%2,%3}, [%4];"
                 : "=r"(r0), "=r"(r1), "=r"(r2), "=r"(r3) : "r"(addr));
}
__device__ __forceinline__ void mma16816(float* c, const uint32_t* a, const uint32_t* b) {
    asm volatile(
        "mma.sync.aligned.m16n8k16.row.col.f32.bf16.bf16.f32 "
        "{%0,%1,%2,%3}, {%4,%5,%6,%7}, {%8,%9}, {%0,%1,%2,%3};"
        : "+f"(c[0]), "+f"(c[1]), "+f"(c[2]), "+f"(c[3])
        : "r"(a[0]), "r"(a[1]), "r"(a[2]), "r"(a[3]), "r"(b[0]), "r"(b[1]));
}

// ---------------------------------------------------------------------------
// Kernel 1: fp32 -> bf16 convert, fused squared norms. One warp per row.
// ---------------------------------------------------------------------------
__global__ void convert_kernel(const float* __restrict__ src,
                               __nv_bfloat16* __restrict__ dst,
                               float* __restrict__ bsq, int rows) {
    int warp = (blockIdx.x * blockDim.x + threadIdx.x) >> 5;
    int lane = threadIdx.x & 31;
    if (warp >= rows) return;
    const float4* srow = reinterpret_cast<const float4*>(src + (size_t)warp * C_DIM);
    __nv_bfloat162* drow = reinterpret_cast<__nv_bfloat162*>(dst + (size_t)warp * C_DIM);
    float acc = 0.f;
#pragma unroll
    for (int i = 0; i < C_DIM / 128; i++) {
        int j = i * 32 + lane;
        float4 v = srow[j];
        acc += v.x * v.x + v.y * v.y + v.z * v.z + v.w * v.w;
        drow[2 * j]     = __nv_bfloat162(__float2bfloat16(v.x), __float2bfloat16(v.y));
        drow[2 * j + 1] = __nv_bfloat162(__float2bfloat16(v.z), __float2bfloat16(v.w));
    }
    if (bsq) {
#pragma unroll
        for (int off = 16; off > 0; off >>= 1)
            acc += __shfl_xor_sync(0xffffffffu, acc, off);
        if (lane == 0) bsq[warp] = acc;
    }
}

// ---------------------------------------------------------------------------
// Kernel 2: coarse bf16 GEMM via mma.sync.m16n8k16. (unchanged, proven)
// ---------------------------------------------------------------------------
#define BM   128
#define BN   128
#define BKC  64
#define NCH  (C_DIM / BKC)
#define TILE_BYTES (BM * 128)
#define GEMM_SMEM  (4 * TILE_BYTES)

__global__ __launch_bounds__(256, 2)
void mma_gemm_kernel(int M) {
    extern __shared__ char smem[];
    const uint32_t sb = smem_to_u32(smem);
    const int tid  = threadIdx.x;
    const int wid  = tid >> 5;
    const int lane = tid & 31;
    const int qt = blockIdx.x;
    const int bn = blockIdx.y * BN;
    const int warp_m = wid & 1;
    const int warp_n = wid >> 1;

    const __nv_bfloat16* Abase = g_q_bf + (size_t)qt * BM * C_DIM;

    int lrow[4], lu[4];
#pragma unroll
    for (int l = 0; l < 4; l++) {
        int id = tid + l * 256;
        lrow[l] = id >> 3;
        lu[l]   = id & 7;
    }

    auto issue_loads = [&](int c, int buf) {
        int k0 = c * BKC;
        uint32_t As = sb + buf * 2 * TILE_BYTES;
        uint32_t Bs = As + TILE_BYTES;
#pragma unroll
        for (int l = 0; l < 4; l++) {
            uint32_t so = SMEM_SWIZZLE_128B((uint32_t)(lrow[l] * 128 + lu[l] * 16));
            cp_async16(As + so, Abase + (size_t)lrow[l] * C_DIM + k0 + lu[l] * 8, 16);
            int n = bn + lrow[l];
            const void* srcB = g_bank_bf + (size_t)(n < M ? n : 0) * C_DIM + k0 + lu[l] * 8;
            cp_async16(Bs + so, srcB, n < M ? 16 : 0);
        }
        cp_commit();
    };

    float acc[4][4][4];
#pragma unroll
    for (int mi = 0; mi < 4; mi++)
#pragma unroll
        for (int nj = 0; nj < 4; nj++)
#pragma unroll
            for (int e = 0; e < 4; e++) acc[mi][nj][e] = 0.f;

    issue_loads(0, 0);

    for (int c = 0; c < NCH; c++) {
        int buf = c & 1;
        if (c + 1 < NCH) {
            issue_loads(c + 1, buf ^ 1);
            cp_wait<1>();
        } else {
            cp_wait<0>();
        }
        __syncthreads();

        uint32_t As = sb + buf * 2 * TILE_BYTES;
        uint32_t Bs = As + TILE_BYTES;
#pragma unroll
        for (int ks = 0; ks < BKC / 16; ks++) {
            uint32_t a[4][4];
            int arow = warp_m * 64 + (lane & 15);
            int akb  = ks * 16 + (lane >> 4) * 8;
#pragma unroll
            for (int mi = 0; mi < 4; mi++) {
                uint32_t so = SMEM_SWIZZLE_128B(
                    (uint32_t)((arow + mi * 16) * 128 + akb * 2));
                ldmx4(a[mi][0], a[mi][1], a[mi][2], a[mi][3], As + so);
            }
            uint32_t b[4][2];
            int g = lane >> 3;
#pragma unroll
            for (int pair = 0; pair < 2; pair++) {
                int brow = warp_n * 32 + pair * 16 + ((g >> 1) & 1) * 8 + (lane & 7);
                int bkb  = ks * 16 + (g & 1) * 8;
                uint32_t so = SMEM_SWIZZLE_128B((uint32_t)(brow * 128 + bkb * 2));
                uint32_t r0, r1, r2, r3;
                ldmx4(r0, r1, r2, r3, Bs + so);
                b[2 * pair][0] = r0; b[2 * pair][1] = r1;
                b[2 * pair + 1][0] = r2; b[2 * pair + 1][1] = r3;
            }
#pragma unroll
            for (int mi = 0; mi < 4; mi++)
#pragma unroll
                for (int nj = 0; nj < 4; nj++)
                    mma16816(acc[mi][nj], a[mi], b[nj]);
        }
        __syncthreads();
    }

    const int qbase = qt * BM + warp_m * 64;
    const int nbase = bn + warp_n * 32;
#pragma unroll
    for (int mi = 0; mi < 4; mi++) {
#pragma unroll
        for (int nj = 0; nj < 4; nj++) {
            int n0 = nbase + nj * 8 + (lane & 3) * 2;
            if (n0 + 1 < M) {
                float b0 = g_bsq[n0], b1 = g_bsq[n0 + 1];
                int q0 = qbase + mi * 16 + (lane >> 2);
                float2 v0 = make_float2(b0 - 2.f * acc[mi][nj][0],
                                        b1 - 2.f * acc[mi][nj][1]);
                float2 v1 = make_float2(b0 - 2.f * acc[mi][nj][2],
                                        b1 - 2.f * acc[mi][nj][3]);
                *reinterpret_cast<float2*>(g_score + (size_t)q0 * M + n0) = v0;
                *reinterpret_cast<float2*>(g_score + (size_t)(q0 + 8) * M + n0) = v1;
            } else if (n0 < M) {
                float b0 = g_bsq[n0];
                int q0 = qbase + mi * 16 + (lane >> 2);
                g_score[(size_t)q0 * M + n0]       = b0 - 2.f * acc[mi][nj][0];
                g_score[(size_t)(q0 + 8) * M + n0] = b0 - 2.f * acc[mi][nj][2];
            }
        }
    }
}

// ---------------------------------------------------------------------------
// Selection helpers
// ---------------------------------------------------------------------------
__device__ __forceinline__ unsigned long long pack_key(float s, int idx) {
    unsigned u = __float_as_uint(s);
    u = (u & 0x80000000u) ? ~u : (u | 0x80000000u);
    return ((unsigned long long)u << 32) | (unsigned)idx;
}
__device__ __forceinline__ float unpack_score(unsigned long long key) {
    unsigned u = (unsigned)(key >> 32);
    u = (u & 0x80000000u) ? (u & 0x7fffffffu) : ~u;
    return __uint_as_float(u);
}
__device__ __forceinline__ unsigned long long warp_min_ull(unsigned long long v) {
#pragma unroll
    for (int off = 16; off > 0; off >>= 1) {
        unsigned long long o = __shfl_xor_sync(0xffffffffu, v, off);
        v = (o < v) ? o : v;
    }
    return v;
}

// ---------------------------------------------------------------------------
// Kernel 3a: per-query threshold from a 3200-element sample (one warp/query).
// T = THR_RANK-th smallest of the sample -> E[#elems <= T] ~ 500 of 200000.
// Also zeroes the append counters.
// ---------------------------------------------------------------------------
__global__ __launch_bounds__(32)
void sample_thresh_kernel(int M) {
    const int q    = blockIdx.x;
    const int lane = threadIdx.x;
    const float4* row4 = reinterpret_cast<const float4*>(g_score + (size_t)q * M);

    float ls[THR_RANK];
#pragma unroll
    for (int j = 0; j < THR_RANK; j++) ls[j] = FLT_MAX;
    for (int j4 = lane; j4 < SAMPLE4; j4 += 32) {
        float4 v = row4[j4];
        float e[4] = {v.x, v.y, v.z, v.w};
#pragma unroll
        for (int t = 0; t < 4; t++) {
            float cs = e[t];
            if (cs < ls[THR_RANK - 1]) {
#pragma unroll
                for (int j = 0; j < THR_RANK; j++) {
                    if (cs < ls[j]) { float ts = ls[j]; ls[j] = cs; cs = ts; }
                }
            }
        }
    }
    // extract THR_RANK-th smallest across warp (values only; ties fine)
    unsigned long long kk[THR_RANK];
#pragma unroll
    for (int j = 0; j < THR_RANK; j++) kk[j] = pack_key(ls[j], lane);
    unsigned long long best = 0;
#pragma unroll
    for (int r = 0; r < THR_RANK; r++) {
        best = warp_min_ull(kk[0]);
        if (kk[0] == best) {
#pragma unroll
            for (int j = 0; j < THR_RANK - 1; j++) kk[j] = kk[j + 1];
            kk[THR_RANK - 1] = ~0ull;
        }
    }
    if (lane == 0) {
        g_thresh[q] = unpack_score(best);
        g_count[q]  = 0;
    }
}

// ---------------------------------------------------------------------------
// Kernel 3b: threshold filter. grid = (32, B). Appends keys <= T to g_list.
// Hot loop is load + fmin tree + compare; append path is rare (~0.8%/vec).
// ---------------------------------------------------------------------------
__global__ __launch_bounds__(256)
void filter_kernel(int M) {
    const int q   = blockIdx.y;
    const int tid = threadIdx.x;
    const float T = g_thresh[q];
    const int M4  = M >> 2;
    const float4* row4 = reinterpret_cast<const float4*>(g_score + (size_t)q * M);
    unsigned long long* list = g_list + (size_t)q * CAP;

    for (int j4 = blockIdx.x * 256 + tid; j4 < M4; j4 += gridDim.x * 256) {
        float4 v = row4[j4];
        float mn = fminf(fminf(v.x, v.y), fminf(v.z, v.w));
        if (mn <= T) {
            int m = j4 * 4;
            float e[4] = {v.x, v.y, v.z, v.w};
#pragma unroll
            for (int t = 0; t < 4; t++) {
                if (e[t] <= T) {
                    int pos = atomicAdd(&g_count[q], 1);
                    if (pos < CAP) list[pos] = pack_key(e[t], m + t);
                }
            }
        }
    }
}

// ---------------------------------------------------------------------------
// Kernel 3c: per-query exact top-64 of the filtered keys.
// Thread-local sorted top-8 -> warp argmin top-32 -> 256-key bitonic.
// ---------------------------------------------------------------------------
__global__ __launch_bounds__(256)
void merge_cand_kernel() {
    const int q    = blockIdx.x;
    const int tid  = threadIdx.x;
    const int wid  = tid >> 5;
    const int lane = tid & 31;
    const int n    = min(g_count[q], CAP);
    const unsigned long long* list = g_list + (size_t)q * CAP;
    __shared__ unsigned long long keys[256];

    unsigned long long kk[8];
#pragma unroll
    for (int j = 0; j < 8; j++) kk[j] = ~0ull;
    for (int t = tid; t < n; t += 256) {
        unsigned long long ck = list[t];
        if (ck < kk[7]) {
#pragma unroll
            for (int j = 0; j < 8; j++) {
                if (ck < kk[j]) { unsigned long long tk = kk[j]; kk[j] = ck; ck = tk; }
            }
        }
    }

    unsigned long long mine = ~0ull;
#pragma unroll
    for (int r = 0; r < 32; r++) {
        unsigned long long best = warp_min_ull(kk[0]);
        if (kk[0] == best && best != ~0ull) {
#pragma unroll
            for (int j = 0; j < 7; j++) kk[j] = kk[j + 1];
            kk[7] = ~0ull;
        }
        if (lane == r) mine = best;
    }
    keys[wid * 32 + lane] = mine;
    __syncthreads();

    for (int k = 2; k <= 256; k <<= 1) {
        for (int j = k >> 1; j > 0; j >>= 1) {
            int ixj = tid ^ j;
            if (ixj > tid) {
                unsigned long long a = keys[tid], b = keys[ixj];
                bool up = ((tid & k) == 0);
                if ((a > b) == up) { keys[tid] = b; keys[ixj] = a; }
            }
            __syncthreads();
        }
    }
    if (tid < NCAND) {
        unsigned long long kv = keys[tid];
        // pad-safe: ~0ull (empty) maps to index 0 (harmless duplicate; occurs
        // only in the astronomically unlikely case count < 64)
        g_cand[q * NCAND + tid] = (kv == ~0ull) ? 0 : (int)(kv & 0xffffffffu);
    }
}

// ---------------------------------------------------------------------------
// Kernel 4: exact fp32 rescore of 64 candidates, top-16, gather trajectories.
// ---------------------------------------------------------------------------
__global__ __launch_bounds__(256)
void rescore_gather_kernel(const float* __restrict__ Q,
                           const float* __restrict__ Bank,
                           const float* __restrict__ traj,
                           float* __restrict__ out, int TD) {
    const int q   = blockIdx.x;
    const int tid = threadIdx.x;
    const int wid = tid >> 5, lane = tid & 31;

    __shared__ __align__(16) float qrow[C_DIM];
    __shared__ float cs[NCAND];
    __shared__ int   ci[NCAND];
    __shared__ unsigned long long k64[NCAND];

    for (int t = tid; t < C_DIM; t += 256)
        qrow[t] = Q[(size_t)q * C_DIM + t];
    __syncthreads();

    const float4* q4 = reinterpret_cast<const float4*>(qrow);
    for (int cand = wid; cand < NCAND; cand += 8) {
        int idx = g_cand[q * NCAND + cand];
        const float4* b4 = reinterpret_cast<const float4*>(Bank + (size_t)idx * C_DIM);
        float acc = 0.f;
#pragma unroll
        for (int j = lane; j < C_DIM / 4; j += 32) {
            float4 a = q4[j], b = b4[j];
            acc += a.x * b.x + a.y * b.y + a.z * b.z + a.w * b.w;
        }
#pragma unroll
        for (int off = 16; off > 0; off >>= 1)
            acc += __shfl_xor_sync(0xffffffffu, acc, off);
        if (lane == 0) { cs[cand] = g_bsq[idx] - 2.0f * acc; ci[cand] = idx; }
    }
    __syncthreads();

    if (tid < NCAND) k64[tid] = pack_key(cs[tid], ci[tid]);
    __syncthreads();
    for (int k = 2; k <= NCAND; k <<= 1) {
        for (int j = k >> 1; j > 0; j >>= 1) {
            for (int t = tid; t < NCAND; t += 256) {
                int ixj = t ^ j;
                if (ixj > t) {
                    unsigned long long a = k64[t], b = k64[ixj];
                    bool up = ((t & k) == 0);
                    if ((a > b) == up) { k64[t] = b; k64[ixj] = a; }
                }
            }
            __syncthreads();
        }
    }

    for (int t = tid; t < KSEL * TD; t += 256) {
        int r = t / TD;
        int c = t - r * TD;
        int idx = (int)(k64[r] & 0xffffffffu);
        out[(size_t)q * KSEL * TD + t] = traj[(size_t)idx * TD + c];
    }
}

// ---------------------------------------------------------------------------
// Launch
// ---------------------------------------------------------------------------
extern "C" void kernel_launch(void* const* d_in, const int* in_sizes, int n_in,
                              void* d_out, int out_size) {
    const float* Q    = (const float*)d_in[0];
    const float* Bank = (const float*)d_in[1];
    const float* Traj = (const float*)d_in[2];
    float* out = (float*)d_out;

    const int C  = C_DIM;
    const int B  = in_sizes[0] / C;    // 256
    const int M  = in_sizes[1] / C;    // 200000
    const int TD = in_sizes[2] / M;    // 24

    cudaFuncSetAttribute(mma_gemm_kernel,
                         cudaFuncAttributeMaxDynamicSharedMemorySize, GEMM_SMEM);

    float* bsq_p = nullptr;
    __nv_bfloat16 *bankbf_p = nullptr, *qbf_p = nullptr;
    cudaGetSymbolAddress((void**)&bsq_p, g_bsq);
    cudaGetSymbolAddress((void**)&bankbf_p, g_bank_bf);
    cudaGetSymbolAddress((void**)&qbf_p, g_q_bf);

    // 1) convert bank (+bsq) and query to bf16
    {
        int ctas = (M * 32 + 255) / 256;
        convert_kernel<<<ctas, 256>>>(Bank, bankbf_p, bsq_p, M);
        int qctas = (B * 32 + 255) / 256;
        convert_kernel<<<qctas, 256>>>(Q, qbf_p, nullptr, B);
    }
    // 2) coarse bf16 mma GEMM
    {
        dim3 grid(B / BM, (M + BN - 1) / BN);
        mma_gemm_kernel<<<grid, 256, GEMM_SMEM>>>(M);
    }
    // 3a) per-query sample threshold (+ counter reset)
    sample_thresh_kernel<<<B, 32>>>(M);
    // 3b) threshold filter
    {
        dim3 grid(32, B);
        filter_kernel<<<grid, 256>>>(M);
    }
    // 3c) exact top-64 of filtered keys
    merge_cand_kernel<<<B, 256>>>();
    // 4) exact fp32 rescore + top-16 + gather
    rescore_gather_kernel<<<B, 256>>>(Q, Bank, Traj, out, TD);
}

// round 14
// speedup vs baseline: 3.0420x; 1.1475x over previous
#include <cuda_runtime.h>
#include <cuda_bf16.h>
#include <cfloat>
#include <climits>
#include <cstdint>

// ---------------------------------------------------------------------------
// Problem shape (fixed):
//   query [B=256,1024] f32, bank [M=200000,1024] f32, traj [M,8,3] f32, k=16
// Output: traj[nn_idx] sorted by ascending L2 dist, ties -> lower index.
// Pipeline:
//   convert -> sample mini-GEMM (26 tiles) -> threshold ->
//   main GEMM with fused threshold-filter epilogue (no score array!) ->
//   exact top-64 of surviving keys -> exact fp32 rescore -> top-16 -> gather.
// ---------------------------------------------------------------------------

#define C_DIM   1024
#define B_MAX   256
#define M_MAX   200000
#define KSEL    16
#define NCAND   64
#define CAP     4096                 // per-query filtered-key capacity
#define SAMPLE_TILES 26
#define SAMPLE_N (SAMPLE_TILES * 128)  // 3328 sampled bank rows
#define THR_RANK 8                   // take 8th smallest of sample

// __device__ scratch (allocation-free rule)
__device__ __align__(16) float          g_sample[(size_t)B_MAX * SAMPLE_N];
__device__ __align__(16) float          g_bsq[M_MAX];
__device__ __align__(16) __nv_bfloat16  g_bank_bf[(size_t)M_MAX * C_DIM];
__device__ __align__(16) __nv_bfloat16  g_q_bf[(size_t)B_MAX * C_DIM];
__device__ __align__(16) unsigned long long g_list[(size_t)B_MAX * CAP];
__device__                int           g_count[B_MAX];
__device__                float         g_thresh[B_MAX];
__device__                int           g_cand[B_MAX * NCAND];

#define SMEM_SWIZZLE_128B(o) ((o) ^ (((o) >> 3) & 0x70))

__device__ __forceinline__ uint32_t smem_to_u32(const void* p) {
    uint32_t a;
    asm("{ .reg .u64 t; cvta.to.shared.u64 t, %1; cvt.u32.u64 %0, t; }"
        : "=r"(a) : "l"(p));
    return a;
}
__device__ __forceinline__ void cp_async16(uint32_t dst, const void* src, int srcsize) {
    asm volatile("cp.async.cg.shared.global [%0], [%1], 16, %2;"
                 :: "r"(dst), "l"(src), "r"(srcsize));
}
__device__ __forceinline__ void cp_commit() {
    asm volatile("cp.async.commit_group;");
}
template <int N>
__device__ __forceinline__ void cp_wait() {
    asm volatile("cp.async.wait_group %0;" :: "n"(N));
}
__device__ __forceinline__ void ldmx4(uint32_t& r0, uint32_t& r1,
                                      uint32_t& r2, uint32_t& r3, uint32_t addr) {
    asm volatile("ldmatrix.sync.aligned.m8n8.x4.shared.b16 {%0,%1,%2,%3}, [%4];"
                 : "=r"(r0), "=r"(r1), "=r"(r2), "=r"(r3) : "r"(addr));
}
__device__ __forceinline__ void mma16816(float* c, const uint32_t* a, const uint32_t* b) {
    asm volatile(
        "mma.sync.aligned.m16n8k16.row.col.f32.bf16.bf16.f32 "
        "{%0,%1,%2,%3}, {%4,%5,%6,%7}, {%8,%9}, {%0,%1,%2,%3};"
        : "+f"(c[0]), "+f"(c[1]), "+f"(c[2]), "+f"(c[3])
        : "r"(a[0]), "r"(a[1]), "r"(a[2]), "r"(a[3]), "r"(b[0]), "r"(b[1]));
}

// ---------------------------------------------------------------------------
// Selection key packing
// ---------------------------------------------------------------------------
__device__ __forceinline__ unsigned long long pack_key(float s, int idx) {
    unsigned u = __float_as_uint(s);
    u = (u & 0x80000000u) ? ~u : (u | 0x80000000u);
    return ((unsigned long long)u << 32) | (unsigned)idx;
}
__device__ __forceinline__ float unpack_score(unsigned long long key) {
    unsigned u = (unsigned)(key >> 32);
    u = (u & 0x80000000u) ? (u & 0x7fffffffu) : ~u;
    return __uint_as_float(u);
}
__device__ __forceinline__ unsigned long long warp_min_ull(unsigned long long v) {
#pragma unroll
    for (int off = 16; off > 0; off >>= 1) {
        unsigned long long o = __shfl_xor_sync(0xffffffffu, v, off);
        v = (o < v) ? o : v;
    }
    return v;
}

// ---------------------------------------------------------------------------
// Kernel 1: fp32 -> bf16 convert, fused squared norms. One warp per row.
// ---------------------------------------------------------------------------
__global__ void convert_kernel(const float* __restrict__ src,
                               __nv_bfloat16* __restrict__ dst,
                               float* __restrict__ bsq, int rows) {
    int warp = (blockIdx.x * blockDim.x + threadIdx.x) >> 5;
    int lane = threadIdx.x & 31;
    if (warp >= rows) return;
    const float4* srow = reinterpret_cast<const float4*>(src + (size_t)warp * C_DIM);
    __nv_bfloat162* drow = reinterpret_cast<__nv_bfloat162*>(dst + (size_t)warp * C_DIM);
    float acc = 0.f;
#pragma unroll
    for (int i = 0; i < C_DIM / 128; i++) {
        int j = i * 32 + lane;
        float4 v = srow[j];
        acc += v.x * v.x + v.y * v.y + v.z * v.z + v.w * v.w;
        drow[2 * j]     = __nv_bfloat162(__float2bfloat16(v.x), __float2bfloat16(v.y));
        drow[2 * j + 1] = __nv_bfloat162(__float2bfloat16(v.z), __float2bfloat16(v.w));
    }
    if (bsq) {
#pragma unroll
        for (int off = 16; off > 0; off >>= 1)
            acc += __shfl_xor_sync(0xffffffffu, acc, off);
        if (lane == 0) bsq[warp] = acc;
    }
}

// ---------------------------------------------------------------------------
// Kernel 2: bf16 GEMM via mma.sync.m16n8k16 with two epilogue modes:
//   mode 0 (sample): write scores to g_sample [B x SAMPLE_N]
//   mode 1 (filter): append keys with score <= g_thresh[q] to g_list
// ---------------------------------------------------------------------------
#define BM   128
#define BN   128
#define BKC  64
#define NCH  (C_DIM / BKC)
#define TILE_BYTES (BM * 128)
#define GEMM_SMEM  (4 * TILE_BYTES)

__global__ __launch_bounds__(256, 2)
void mma_gemm_kernel(int M, int mode) {
    extern __shared__ char smem[];
    const uint32_t sb = smem_to_u32(smem);
    const int tid  = threadIdx.x;
    const int wid  = tid >> 5;
    const int lane = tid & 31;
    const int qt = blockIdx.x;
    const int bn = blockIdx.y * BN;
    const int warp_m = wid & 1;
    const int warp_n = wid >> 1;

    const __nv_bfloat16* Abase = g_q_bf + (size_t)qt * BM * C_DIM;

    int lrow[4], lu[4];
#pragma unroll
    for (int l = 0; l < 4; l++) {
        int id = tid + l * 256;
        lrow[l] = id >> 3;
        lu[l]   = id & 7;
    }

    auto issue_loads = [&](int c, int buf) {
        int k0 = c * BKC;
        uint32_t As = sb + buf * 2 * TILE_BYTES;
        uint32_t Bs = As + TILE_BYTES;
#pragma unroll
        for (int l = 0; l < 4; l++) {
            uint32_t so = SMEM_SWIZZLE_128B((uint32_t)(lrow[l] * 128 + lu[l] * 16));
            cp_async16(As + so, Abase + (size_t)lrow[l] * C_DIM + k0 + lu[l] * 8, 16);
            int n = bn + lrow[l];
            const void* srcB = g_bank_bf + (size_t)(n < M ? n : 0) * C_DIM + k0 + lu[l] * 8;
            cp_async16(Bs + so, srcB, n < M ? 16 : 0);
        }
        cp_commit();
    };

    float acc[4][4][4];
#pragma unroll
    for (int mi = 0; mi < 4; mi++)
#pragma unroll
        for (int nj = 0; nj < 4; nj++)
#pragma unroll
            for (int e = 0; e < 4; e++) acc[mi][nj][e] = 0.f;

    issue_loads(0, 0);

    for (int c = 0; c < NCH; c++) {
        int buf = c & 1;
        if (c + 1 < NCH) {
            issue_loads(c + 1, buf ^ 1);
            cp_wait<1>();
        } else {
            cp_wait<0>();
        }
        __syncthreads();

        uint32_t As = sb + buf * 2 * TILE_BYTES;
        uint32_t Bs = As + TILE_BYTES;
#pragma unroll
        for (int ks = 0; ks < BKC / 16; ks++) {
            uint32_t a[4][4];
            int arow = warp_m * 64 + (lane & 15);
            int akb  = ks * 16 + (lane >> 4) * 8;
#pragma unroll
            for (int mi = 0; mi < 4; mi++) {
                uint32_t so = SMEM_SWIZZLE_128B(
                    (uint32_t)((arow + mi * 16) * 128 + akb * 2));
                ldmx4(a[mi][0], a[mi][1], a[mi][2], a[mi][3], As + so);
            }
            uint32_t b[4][2];
            int g = lane >> 3;
#pragma unroll
            for (int pair = 0; pair < 2; pair++) {
                int brow = warp_n * 32 + pair * 16 + ((g >> 1) & 1) * 8 + (lane & 7);
                int bkb  = ks * 16 + (g & 1) * 8;
                uint32_t so = SMEM_SWIZZLE_128B((uint32_t)(brow * 128 + bkb * 2));
                uint32_t r0, r1, r2, r3;
                ldmx4(r0, r1, r2, r3, Bs + so);
                b[2 * pair][0] = r0; b[2 * pair][1] = r1;
                b[2 * pair + 1][0] = r2; b[2 * pair + 1][1] = r3;
            }
#pragma unroll
            for (int mi = 0; mi < 4; mi++)
#pragma unroll
                for (int nj = 0; nj < 4; nj++)
                    mma16816(acc[mi][nj], a[mi], b[nj]);
        }
        __syncthreads();
    }

    const int qbase = qt * BM + warp_m * 64;
    const int nbase = bn + warp_n * 32;

    if (mode == 0) {
        // sample epilogue: write scores into g_sample (row stride SAMPLE_N)
#pragma unroll
        for (int mi = 0; mi < 4; mi++) {
            int q0 = qbase + mi * 16 + (lane >> 2);
#pragma unroll
            for (int nj = 0; nj < 4; nj++) {
                int n0 = nbase + nj * 8 + (lane & 3) * 2;
                float b0 = g_bsq[n0], b1 = g_bsq[n0 + 1];
                float2 v0 = make_float2(b0 - 2.f * acc[mi][nj][0],
                                        b1 - 2.f * acc[mi][nj][1]);
                float2 v1 = make_float2(b0 - 2.f * acc[mi][nj][2],
                                        b1 - 2.f * acc[mi][nj][3]);
                *reinterpret_cast<float2*>(g_sample + (size_t)q0 * SAMPLE_N + n0) = v0;
                *reinterpret_cast<float2*>(g_sample + (size_t)(q0 + 8) * SAMPLE_N + n0) = v1;
            }
        }
    } else {
        // filter epilogue: append survivors (score <= per-query threshold)
#pragma unroll
        for (int mi = 0; mi < 4; mi++) {
            int q0 = qbase + mi * 16 + (lane >> 2);
            int q1 = q0 + 8;
            float T0 = g_thresh[q0];
            float T1 = g_thresh[q1];
#pragma unroll
            for (int nj = 0; nj < 4; nj++) {
                int n0 = nbase + nj * 8 + (lane & 3) * 2;
                if (n0 < M) {
                    float b0 = g_bsq[n0];
                    float s00 = b0 - 2.f * acc[mi][nj][0];
                    float s10 = b0 - 2.f * acc[mi][nj][2];
                    if (s00 <= T0) {
                        int pos = atomicAdd(&g_count[q0], 1);
                        if (pos < CAP) g_list[(size_t)q0 * CAP + pos] = pack_key(s00, n0);
                    }
                    if (s10 <= T1) {
                        int pos = atomicAdd(&g_count[q1], 1);
                        if (pos < CAP) g_list[(size_t)q1 * CAP + pos] = pack_key(s10, n0);
                    }
                    if (n0 + 1 < M) {
                        float b1 = g_bsq[n0 + 1];
                        float s01 = b1 - 2.f * acc[mi][nj][1];
                        float s11 = b1 - 2.f * acc[mi][nj][3];
                        if (s01 <= T0) {
                            int pos = atomicAdd(&g_count[q0], 1);
                            if (pos < CAP) g_list[(size_t)q0 * CAP + pos] = pack_key(s01, n0 + 1);
                        }
                        if (s11 <= T1) {
                            int pos = atomicAdd(&g_count[q1], 1);
                            if (pos < CAP) g_list[(size_t)q1 * CAP + pos] = pack_key(s11, n0 + 1);
                        }
                    }
                }
            }
        }
    }
}

// ---------------------------------------------------------------------------
// Kernel 3: per-query threshold = THR_RANK-th smallest of the sample row.
// 8 warps scan slices -> 64 keys -> warp 0 extracts rank-8. Resets counter.
// ---------------------------------------------------------------------------
__global__ __launch_bounds__(256)
void sample_thresh_kernel() {
    const int q    = blockIdx.x;
    const int tid  = threadIdx.x;
    const int wid  = tid >> 5;
    const int lane = tid & 31;
    const float4* row4 = reinterpret_cast<const float4*>(g_sample + (size_t)q * SAMPLE_N);
    const int N4 = SAMPLE_N / 4;             // 832
    __shared__ unsigned long long wkeys[64];

    // per-lane sorted top-8 over this warp's slice
    float ls[THR_RANK];
#pragma unroll
    for (int j = 0; j < THR_RANK; j++) ls[j] = FLT_MAX;
    const int per_warp = (N4 + 7) / 8;       // 104
    const int j0 = wid * per_warp;
    const int j1 = min(N4, j0 + per_warp);
    for (int j4 = j0 + lane; j4 < j1; j4 += 32) {
        float4 v = row4[j4];
        float e[4] = {v.x, v.y, v.z, v.w};
#pragma unroll
        for (int t = 0; t < 4; t++) {
            float cs = e[t];
            if (cs < ls[THR_RANK - 1]) {
#pragma unroll
                for (int j = 0; j < THR_RANK; j++) {
                    if (cs < ls[j]) { float ts = ls[j]; ls[j] = cs; cs = ts; }
                }
            }
        }
    }
    // warp top-8 via argmin rounds (keys unique: embed lane+warp)
    unsigned long long kk[THR_RANK];
#pragma unroll
    for (int j = 0; j < THR_RANK; j++) kk[j] = pack_key(ls[j], (wid << 8) | (lane << 3) | j);
    unsigned long long mine = ~0ull;
#pragma unroll
    for (int r = 0; r < THR_RANK; r++) {
        unsigned long long best = warp_min_ull(kk[0]);
        if (kk[0] == best) {
#pragma unroll
            for (int j = 0; j < THR_RANK - 1; j++) kk[j] = kk[j + 1];
            kk[THR_RANK - 1] = ~0ull;
        }
        if (lane == r) mine = best;
    }
    if (lane < THR_RANK) wkeys[wid * THR_RANK + lane] = mine;
    __syncthreads();

    if (wid == 0) {
        // 64 keys, 2 per lane, sorted pair; 8 argmin-removal rounds
        unsigned long long p0 = wkeys[lane], p1 = wkeys[32 + lane];
        if (p1 < p0) { unsigned long long t = p0; p0 = p1; p1 = t; }
        unsigned long long best = 0;
#pragma unroll
        for (int r = 0; r < THR_RANK; r++) {
            best = warp_min_ull(p0);
            if (p0 == best) { p0 = p1; p1 = ~0ull; }
        }
        if (lane == 0) {
            g_thresh[q] = unpack_score(best);
            g_count[q]  = 0;
        }
    }
}

// ---------------------------------------------------------------------------
// Kernel 4: per-query exact top-64 of the filtered keys.
// ---------------------------------------------------------------------------
__global__ __launch_bounds__(256)
void merge_cand_kernel() {
    const int q    = blockIdx.x;
    const int tid  = threadIdx.x;
    const int wid  = tid >> 5;
    const int lane = tid & 31;
    const int n    = min(g_count[q], CAP);
    const unsigned long long* list = g_list + (size_t)q * CAP;
    __shared__ unsigned long long keys[256];

    unsigned long long kk[8];
#pragma unroll
    for (int j = 0; j < 8; j++) kk[j] = ~0ull;
    for (int t = tid; t < n; t += 256) {
        unsigned long long ck = list[t];
        if (ck < kk[7]) {
#pragma unroll
            for (int j = 0; j < 8; j++) {
                if (ck < kk[j]) { unsigned long long tk = kk[j]; kk[j] = ck; ck = tk; }
            }
        }
    }

    unsigned long long mine = ~0ull;
#pragma unroll
    for (int r = 0; r < 32; r++) {
        unsigned long long best = warp_min_ull(kk[0]);
        if (kk[0] == best && best != ~0ull) {
#pragma unroll
            for (int j = 0; j < 7; j++) kk[j] = kk[j + 1];
            kk[7] = ~0ull;
        }
        if (lane == r) mine = best;
    }
    keys[wid * 32 + lane] = mine;
    __syncthreads();

    for (int k = 2; k <= 256; k <<= 1) {
        for (int j = k >> 1; j > 0; j >>= 1) {
            int ixj = tid ^ j;
            if (ixj > tid) {
                unsigned long long a = keys[tid], b = keys[ixj];
                bool up = ((tid & k) == 0);
                if ((a > b) == up) { keys[tid] = b; keys[ixj] = a; }
            }
            __syncthreads();
        }
    }
    if (tid < NCAND) {
        unsigned long long kv = keys[tid];
        g_cand[q * NCAND + tid] = (kv == ~0ull) ? 0 : (int)(kv & 0xffffffffu);
    }
}

// ---------------------------------------------------------------------------
// Kernel 5: exact fp32 rescore of 64 candidates, top-16, gather trajectories.
// ---------------------------------------------------------------------------
__global__ __launch_bounds__(256)
void rescore_gather_kernel(const float* __restrict__ Q,
                           const float* __restrict__ Bank,
                           const float* __restrict__ traj,
                           float* __restrict__ out, int TD) {
    const int q   = blockIdx.x;
    const int tid = threadIdx.x;
    const int wid = tid >> 5, lane = tid & 31;

    __shared__ __align__(16) float qrow[C_DIM];
    __shared__ float cs[NCAND];
    __shared__ int   ci[NCAND];
    __shared__ unsigned long long k64[NCAND];

    for (int t = tid; t < C_DIM; t += 256)
        qrow[t] = Q[(size_t)q * C_DIM + t];
    __syncthreads();

    const float4* q4 = reinterpret_cast<const float4*>(qrow);
    for (int cand = wid; cand < NCAND; cand += 8) {
        int idx = g_cand[q * NCAND + cand];
        const float4* b4 = reinterpret_cast<const float4*>(Bank + (size_t)idx * C_DIM);
        float acc = 0.f;
#pragma unroll
        for (int j = lane; j < C_DIM / 4; j += 32) {
            float4 a = q4[j], b = b4[j];
            acc += a.x * b.x + a.y * b.y + a.z * b.z + a.w * b.w;
        }
#pragma unroll
        for (int off = 16; off > 0; off >>= 1)
            acc += __shfl_xor_sync(0xffffffffu, acc, off);
        if (lane == 0) { cs[cand] = g_bsq[idx] - 2.0f * acc; ci[cand] = idx; }
    }
    __syncthreads();

    if (tid < NCAND) k64[tid] = pack_key(cs[tid], ci[tid]);
    __syncthreads();
    for (int k = 2; k <= NCAND; k <<= 1) {
        for (int j = k >> 1; j > 0; j >>= 1) {
            for (int t = tid; t < NCAND; t += 256) {
                int ixj = t ^ j;
                if (ixj > t) {
                    unsigned long long a = k64[t], b = k64[ixj];
                    bool up = ((t & k) == 0);
                    if ((a > b) == up) { k64[t] = b; k64[ixj] = a; }
                }
            }
            __syncthreads();
        }
    }

    for (int t = tid; t < KSEL * TD; t += 256) {
        int r = t / TD;
        int c = t - r * TD;
        int idx = (int)(k64[r] & 0xffffffffu);
        out[(size_t)q * KSEL * TD + t] = traj[(size_t)idx * TD + c];
    }
}

// ---------------------------------------------------------------------------
// Launch
// ---------------------------------------------------------------------------
extern "C" void kernel_launch(void* const* d_in, const int* in_sizes, int n_in,
                              void* d_out, int out_size) {
    const float* Q    = (const float*)d_in[0];
    const float* Bank = (const float*)d_in[1];
    const float* Traj = (const float*)d_in[2];
    float* out = (float*)d_out;

    const int C  = C_DIM;
    const int B  = in_sizes[0] / C;    // 256
    const int M  = in_sizes[1] / C;    // 200000
    const int TD = in_sizes[2] / M;    // 24

    cudaFuncSetAttribute(mma_gemm_kernel,
                         cudaFuncAttributeMaxDynamicSharedMemorySize, GEMM_SMEM);

    float* bsq_p = nullptr;
    __nv_bfloat16 *bankbf_p = nullptr, *qbf_p = nullptr;
    cudaGetSymbolAddress((void**)&bsq_p, g_bsq);
    cudaGetSymbolAddress((void**)&bankbf_p, g_bank_bf);
    cudaGetSymbolAddress((void**)&qbf_p, g_q_bf);

    // 1) convert bank (+bsq) and query to bf16
    {
        int ctas = (M * 32 + 255) / 256;
        convert_kernel<<<ctas, 256>>>(Bank, bankbf_p, bsq_p, M);
        int qctas = (B * 32 + 255) / 256;
        convert_kernel<<<qctas, 256>>>(Q, qbf_p, nullptr, B);
    }
    // 2) sample mini-GEMM over first SAMPLE_N bank rows
    {
        dim3 grid(B / BM, SAMPLE_TILES);
        mma_gemm_kernel<<<grid, 256, GEMM_SMEM>>>(M, 0);
    }
    // 3) per-query threshold + counter reset
    sample_thresh_kernel<<<B, 256>>>();
    // 4) main GEMM with fused threshold-filter epilogue
    {
        dim3 grid(B / BM, (M + BN - 1) / BN);
        mma_gemm_kernel<<<grid, 256, GEMM_SMEM>>>(M, 1);
    }
    // 5) exact top-64 of filtered keys
    merge_cand_kernel<<<B, 256>>>();
    // 6) exact fp32 rescore + top-16 + gather
    rescore_gather_kernel<<<B, 256>>>(Q, Bank, Traj, out, TD);
}